// round 17
// baseline (speedup 1.0000x reference)
#include <cuda_runtime.h>
#include <math.h>

// Problem constants
constexpr int BSZ = 64;     // batch
constexpr int SEQ = 512;    // sequence length
constexpr int IN  = 512;    // input dim
constexpr int HD  = 1024;   // hidden dim
constexpr int G4  = 4 * HD; // 4096 gate columns

constexpr int NCTAS = 128;  // persistent grid (1 CTA per SM)
constexpr int NTHR  = 512;  // 16 warps: 4-way K-split (4 warps per quarter)
constexpr int KQ    = 256;  // K range per quarter

constexpr int HBUF = BSZ * HD;   // one h buffer

// Scratch: xg = x @ Xcat + bcat, layout [m = b*SEQ + t][gate*HD + j]
__device__ float g_xg[(size_t)BSZ * SEQ * G4];   // 512 MB
__device__ float g_h[2 * HBUF];                  // double-buffered h (race-free)
__device__ unsigned g_count;
__device__ unsigned g_phase;

// Dynamic SMEM layout (bytes):
//   Bs: [1024][32] floats              @ 0      (131072 B) -- Hcat slice, loaded once
//   As: [4 quarters][2 bufs][64][20]   @ 131072 (40960 B)  -- per-quarter h chunks (16 kk)
//   Gs: [4 quarters][64][36]           @ 172032 (36864 B)  -- per-quarter partial g
constexpr int AS_STRIDE = 20;             // 16 kk + 4 pad floats
constexpr int AS_CHUNK  = 64 * AS_STRIDE; // 1280 floats
constexpr int AS_QBUF   = 2 * AS_CHUNK;   // 2560 floats per quarter
constexpr int SMEM_BS   = 0;
constexpr int SMEM_AS   = 131072;
constexpr int SMEM_GS   = 131072 + 4 * AS_QBUF * 4;   // 172032
constexpr int GS_Q      = 64 * 36;        // floats per quarter tile
constexpr int SMEM_TOTAL = SMEM_GS + 4 * GS_Q * 4;    // 208896 B

#define FMA2(acc, a, b) asm("fma.rn.f32x2 %0,%1,%2,%0;" : "+l"(acc) : "l"(a), "l"(b))

// Fast gate functions: __expf-based, saturate correctly at extremes.
__device__ __forceinline__ float fast_sigmoid(float x) {
    return __fdividef(1.0f, 1.0f + __expf(-x));
}
__device__ __forceinline__ float fast_tanh(float x) {
    return 1.0f - __fdividef(2.0f, __expf(2.0f * x) + 1.0f);
}

// ---------------------------------------------------------------------------
// Zero h buffers and barrier state
// ---------------------------------------------------------------------------
__global__ void init_state_kernel() {
    int i = blockIdx.x * blockDim.x + threadIdx.x;
    if (i < 2 * HBUF) g_h[i] = 0.0f;
    if (i == 0) { g_count = 0u; g_phase = 0u; }
}

// ---------------------------------------------------------------------------
// ncu alignment dummy: keeps the capture window on the persistent kernel.
// ---------------------------------------------------------------------------
__global__ void ncu_align_kernel() {}

// ---------------------------------------------------------------------------
// Input projection, FFMA2 (unchanged, proven)
// ---------------------------------------------------------------------------
__global__ __launch_bounds__(256, 4)
void xproj_kernel(const float* __restrict__ x,
                  const float* __restrict__ X1, const float* __restrict__ X2,
                  const float* __restrict__ X3, const float* __restrict__ X4,
                  const float* __restrict__ b1, const float* __restrict__ b2,
                  const float* __restrict__ b3, const float* __restrict__ b4)
{
    const int gate = blockIdx.z;
    const float* __restrict__ Xg = (gate == 0) ? X1 : (gate == 1) ? X2 : (gate == 2) ? X3 : X4;
    const float* __restrict__ bg = (gate == 0) ? b1 : (gate == 1) ? b2 : (gate == 2) ? b3 : b4;

    const int m0 = blockIdx.y * 64;
    const int n0 = blockIdx.x * 64;

    __shared__ float As[16][68];   // [k][m], padded stride 68
    __shared__ float Bs[16][64];   // [k][n]

    const int tid = threadIdx.x;
    const int tx = tid & 15;       // 4 n-cols each (2 f32x2 pairs)
    const int ty = tid >> 4;       // 4 m-rows each

    unsigned long long acc[4][2];
    #pragma unroll
    for (int r = 0; r < 4; r++) { acc[r][0] = 0ull; acc[r][1] = 0ull; }

    for (int k0 = 0; k0 < IN; k0 += 16) {
        {
            int row = tid >> 2;
            int kq  = tid & 3;
            float4 v = *(const float4*)(x + (size_t)(m0 + row) * IN + k0 + kq * 4);
            As[kq * 4 + 0][row] = v.x;
            As[kq * 4 + 1][row] = v.y;
            As[kq * 4 + 2][row] = v.z;
            As[kq * 4 + 3][row] = v.w;
        }
        {
            int kr = tid >> 4;
            int nq = tid & 15;
            float4 v = *(const float4*)(Xg + (size_t)(k0 + kr) * HD + n0 + nq * 4);
            *(float4*)&Bs[kr][nq * 4] = v;
        }
        __syncthreads();

        #pragma unroll
        for (int k = 0; k < 16; k++) {
            float4 a4 = *(const float4*)&As[k][ty * 4];
            ulonglong2 b = *(const ulonglong2*)&Bs[k][tx * 4];

            unsigned long long aa0, aa1, aa2, aa3;
            asm("mov.b64 %0,{%1,%1};" : "=l"(aa0) : "f"(a4.x));
            asm("mov.b64 %0,{%1,%1};" : "=l"(aa1) : "f"(a4.y));
            asm("mov.b64 %0,{%1,%1};" : "=l"(aa2) : "f"(a4.z));
            asm("mov.b64 %0,{%1,%1};" : "=l"(aa3) : "f"(a4.w));

            FMA2(acc[0][0], aa0, b.x); FMA2(acc[0][1], aa0, b.y);
            FMA2(acc[1][0], aa1, b.x); FMA2(acc[1][1], aa1, b.y);
            FMA2(acc[2][0], aa2, b.x); FMA2(acc[2][1], aa2, b.y);
            FMA2(acc[3][0], aa3, b.x); FMA2(acc[3][1], aa3, b.y);
        }
        __syncthreads();
    }

    #pragma unroll
    for (int r = 0; r < 4; r++) {
        int m = m0 + ty * 4 + r;
        size_t base = (size_t)m * G4 + (size_t)gate * HD + n0 + tx * 4;
        float f0, f1, f2, f3;
        asm("mov.b64 {%0,%1},%2;" : "=f"(f0), "=f"(f1) : "l"(acc[r][0]));
        asm("mov.b64 {%0,%1},%2;" : "=f"(f2), "=f"(f3) : "l"(acc[r][1]));
        g_xg[base + 0] = f0 + bg[n0 + tx * 4 + 0];
        g_xg[base + 1] = f1 + bg[n0 + tx * 4 + 1];
        g_xg[base + 2] = f2 + bg[n0 + tx * 4 + 2];
        g_xg[base + 3] = f3 + bg[n0 + tx * 4 + 3];
    }
}

// ---------------------------------------------------------------------------
// Software grid barrier (proven R12 version, unchanged)
// ---------------------------------------------------------------------------
__device__ __forceinline__ unsigned ld_cg_u32(const unsigned* p) {
    unsigned v;
    asm volatile("ld.global.cg.u32 %0,[%1];" : "=r"(v) : "l"(p));
    return v;
}

__device__ __forceinline__ void grid_sync(unsigned target) {
    __syncthreads();
    if (threadIdx.x == 0) {
        __threadfence();                      // publish h/out stores (required)
        if (atomicAdd(&g_count, 1u) == NCTAS - 1) {
            atomicExch(&g_count, 0u);
            __threadfence();
            atomicExch(&g_phase, target);
        } else {
            while (ld_cg_u32(&g_phase) < target) { __nanosleep(64); }
        }
        // no trailing fence: h reads are __ldcg (L2-direct), never stale L1
    }
    __syncthreads();
}

// ---------------------------------------------------------------------------
// Persistent recurrence kernel, 4-WAY K-SPLIT (16 warps, 4 per SMSP):
//   quarter q (warps 4q..4q+3) accumulates K in [q*256,(q+1)*256) for the
//   SAME 64x32 tile. Traffic per SM identical to the proven kernel; per-warp
//   instruction count halves vs the 2-way split, and 4 warps/SMSP interleave
//   to hide LDS/LDG latency. Partials combine via 4 Gs tiles.
// Inner-loop shape (conflict-free A LDS.128, broadcast B LDS.128, FFMA2)
// identical to the proven 13.28ms kernel; chunk size 16 kk to fit SMEM.
// ---------------------------------------------------------------------------
__global__ void __launch_bounds__(NTHR, 1)
lstm_persistent_kernel(const float* __restrict__ H1, const float* __restrict__ H2,
                       const float* __restrict__ H3, const float* __restrict__ H4,
                       float* __restrict__ out)
{
    extern __shared__ char smem[];
    float* Bs = (float*)(smem + SMEM_BS);   // [k][c], c = gate*8 + jj, stride 32
    float* As = (float*)(smem + SMEM_AS);   // [quarter][buf][row][kk], stride 20
    float* Gs = (float*)(smem + SMEM_GS);   // [quarter][row][col], stride 36

    const int tid     = threadIdx.x;
    const int quarter = tid >> 7;            // 0..3 -> K range
    const int hid     = tid & 127;           // id within quarter
    const int tx      = hid & 7;             // 4 tile-cols each
    const int ty      = hid >> 3;            // 0..15
    const int j0      = blockIdx.x * 8;
    const int kbase   = quarter * KQ;

    float* Aq = As + quarter * AS_QBUF;      // this quarter's double-buffered A
    float* Gq = Gs + quarter * GS_Q;         // this quarter's partial g

    // ---- Load Hcat slice (32 cols x 1024 k) into SMEM once (512 threads) ----
    {
        const int bk  = tid >> 2;           // 0..127 k-rows per pass
        const int bgt = tid & 3;            // gate
        const float* __restrict__ Hg = (bgt == 0) ? H1 : (bgt == 1) ? H2 : (bgt == 2) ? H3 : H4;
        for (int k0 = 0; k0 < HD; k0 += 128) {
            const float* src = Hg + (size_t)(k0 + bk) * HD + j0;
            float4 v0 = *(const float4*)(src);
            float4 v1 = *(const float4*)(src + 4);
            *(float4*)&Bs[(k0 + bk) * 32 + bgt * 8]     = v0;
            *(float4*)&Bs[(k0 + bk) * 32 + bgt * 8 + 4] = v1;
        }
    }

    // ---- Per-thread epilogue slot: 1 (b, j) pair (512 threads = 512 slots) ----
    const int b_ep  = tid >> 3;             // 0..63
    const int jj_ep = tid & 7;
    const int j_ep  = j0 + jj_ep;
    const float* xptr = g_xg + (size_t)b_ep * SEQ * G4 + j_ep;
    const int    hoff = b_ep * HD + j_ep;
    float*       optr = out + (size_t)b_ep * SEQ * HD + j_ep;
    const int    goff = b_ep * 36 + jj_ep;
    float        c_reg = 0.f;

    // ---- A-staging slots: 2 float4 per thread per 64x16 chunk ----
    int aoff_g[2];                          // h-buffer offset (row*HD + kbase + kq*4)
    int aoff_s[2];                          // As offset within quarter (row*20 + kq*4)
    #pragma unroll
    for (int i = 0; i < 2; i++) {
        int q   = hid + 128 * i;            // 0..255
        int row = q >> 2;                   // 0..63
        int kq  = q & 3;                    // 0..3
        aoff_g[i] = row * HD + kbase + kq * 4;
        aoff_s[i] = row * AS_STRIDE + kq * 4;
    }

    __syncthreads();                        // Bs ready

    for (int t = 0; t < SEQ; t++) {
        const float* hrd = g_h + (size_t)(t & 1) * HBUF;          // h_{t-1}
        float*       hwr = g_h + (size_t)((t + 1) & 1) * HBUF;    // h_t

        // ---- Prefetch xg (DRAM) — hides under the K loop ----
        const float* xp = xptr + (size_t)t * G4;
        float xf = __ldg(xp);
        float xi = __ldg(xp + HD);
        float xc = __ldg(xp + 2 * HD);
        float xo = __ldg(xp + 3 * HD);

        unsigned long long acc0[4] = {0ull, 0ull, 0ull, 0ull};  // cols tx*4+0,1
        unsigned long long acc1[4] = {0ull, 0ull, 0ull, 0ull};  // cols tx*4+2,3

        // ---- Prologue: stage chunk 0 of this quarter, prefetch chunk 1 ----
        float4 v[2];
        #pragma unroll
        for (int i = 0; i < 2; i++) v[i] = __ldcg((const float4*)(hrd + aoff_g[i]));
        #pragma unroll
        for (int i = 0; i < 2; i++) *(float4*)&Aq[aoff_s[i]] = v[i];
        #pragma unroll
        for (int i = 0; i < 2; i++) v[i] = __ldcg((const float4*)(hrd + aoff_g[i] + 16));
        __syncthreads();

        // 16 chunks of 16 k per quarter
        for (int ch = 0; ch < 16; ch++) {
            if (ch + 1 < 16) {
                const int nb = ((ch + 1) & 1) * AS_CHUNK;
                #pragma unroll
                for (int i = 0; i < 2; i++) *(float4*)&Aq[nb + aoff_s[i]] = v[i];
            }
            if (ch + 2 < 16) {
                const int gk = (ch + 2) * 16;
                #pragma unroll
                for (int i = 0; i < 2; i++)
                    v[i] = __ldcg((const float4*)(hrd + aoff_g[i] + gk));
            }

            const float* Ab = Aq + (ch & 1) * AS_CHUNK;
            const float* Bb = Bs + (kbase + ch * 16) * 32 + tx * 4;

            #pragma unroll
            for (int k4 = 0; k4 < 4; k4++) {
                // One LDS.128 per row: conflict-free (banks 20*ty + 4*k4 spans)
                float a0v[4], a1v[4], a2v[4], a3v[4];
                *(float4*)a0v = *(const float4*)&Ab[(ty +  0) * AS_STRIDE + k4 * 4];
                *(float4*)a1v = *(const float4*)&Ab[(ty + 16) * AS_STRIDE + k4 * 4];
                *(float4*)a2v = *(const float4*)&Ab[(ty + 32) * AS_STRIDE + k4 * 4];
                *(float4*)a3v = *(const float4*)&Ab[(ty + 48) * AS_STRIDE + k4 * 4];

                #pragma unroll
                for (int e = 0; e < 4; e++) {
                    ulonglong2 bb = *(const ulonglong2*)(Bb + (k4 * 4 + e) * 32);

                    unsigned long long aa0, aa1, aa2, aa3;
                    asm("mov.b64 %0,{%1,%1};" : "=l"(aa0) : "f"(a0v[e]));
                    asm("mov.b64 %0,{%1,%1};" : "=l"(aa1) : "f"(a1v[e]));
                    asm("mov.b64 %0,{%1,%1};" : "=l"(aa2) : "f"(a2v[e]));
                    asm("mov.b64 %0,{%1,%1};" : "=l"(aa3) : "f"(a3v[e]));

                    FMA2(acc0[0], aa0, bb.x); FMA2(acc1[0], aa0, bb.y);
                    FMA2(acc0[1], aa1, bb.x); FMA2(acc1[1], aa1, bb.y);
                    FMA2(acc0[2], aa2, bb.x); FMA2(acc1[2], aa2, bb.y);
                    FMA2(acc0[3], aa3, bb.x); FMA2(acc1[3], aa3, bb.y);
                }
            }
            __syncthreads();
        }

        // ---- Stage partial g tile for this quarter ----
        #pragma unroll
        for (int r = 0; r < 4; r++) {
            float f0, f1, f2, f3;
            asm("mov.b64 {%0,%1},%2;" : "=f"(f0), "=f"(f1) : "l"(acc0[r]));
            asm("mov.b64 {%0,%1},%2;" : "=f"(f2), "=f"(f3) : "l"(acc1[r]));
            float4 g4v = make_float4(f0, f1, f2, f3);
            *(float4*)&Gq[(ty + 16 * r) * 36 + tx * 4] = g4v;
        }
        __syncthreads();

        // ---- Epilogue: combine 4 quarter partials, gates, c/h update ----
        {
            const float* G0 = Gs;
            const float* G1 = Gs + GS_Q;
            const float* G2 = Gs + 2 * GS_Q;
            const float* G3 = Gs + 3 * GS_Q;

            float gf = ((G0[goff +  0] + G1[goff +  0]) + (G2[goff +  0] + G3[goff +  0])) + xf;
            float gi = ((G0[goff +  8] + G1[goff +  8]) + (G2[goff +  8] + G3[goff +  8])) + xi;
            float gc = ((G0[goff + 16] + G1[goff + 16]) + (G2[goff + 16] + G3[goff + 16])) + xc;
            float gg = ((G0[goff + 24] + G1[goff + 24]) + (G2[goff + 24] + G3[goff + 24])) + xo;

            float s1 = fast_sigmoid(gf);
            float s2 = fast_sigmoid(gi);
            float t1 = fast_tanh(gc);
            float s3 = fast_sigmoid(gg);

            c_reg = c_reg * s1 + s2 * t1;
            float hnew = fast_tanh(c_reg) * s3;

            hwr[hoff] = hnew;
            optr[(size_t)t * HD] = hnew;
        }

        // ---- Grid-wide barrier before next step reads updated h ----
        if (t + 1 < SEQ) grid_sync((unsigned)(t + 1));
    }
}

// ---------------------------------------------------------------------------
// Launch
// ---------------------------------------------------------------------------
extern "C" void kernel_launch(void* const* d_in, const int* in_sizes, int n_in,
                              void* d_out, int out_size)
{
    const float* x  = (const float*)d_in[0];
    const float* X1 = (const float*)d_in[1];
    const float* H1 = (const float*)d_in[2];
    const float* b1 = (const float*)d_in[3];
    const float* X2 = (const float*)d_in[4];
    const float* H2 = (const float*)d_in[5];
    const float* b2 = (const float*)d_in[6];
    const float* X3 = (const float*)d_in[7];
    const float* H3 = (const float*)d_in[8];
    const float* b3 = (const float*)d_in[9];
    const float* X4 = (const float*)d_in[10];
    const float* H4 = (const float*)d_in[11];
    const float* b4 = (const float*)d_in[12];
    float* out = (float*)d_out;

    cudaFuncSetAttribute(lstm_persistent_kernel,
                         cudaFuncAttributeMaxDynamicSharedMemorySize, SMEM_TOTAL);

    // Zero recurrent state (both buffers) + barrier
    init_state_kernel<<<(2 * HBUF + 255) / 256, 256>>>();

    // Input projection: xg = x @ Xcat + bcat (FFMA2 GEMM)
    dim3 grid_x(HD / 64, (BSZ * SEQ) / 64, 4);
    xproj_kernel<<<grid_x, 256>>>(x, X1, X2, X3, X4, b1, b2, b3, b4);

    // ncu alignment: keep capture window on the persistent kernel
    ncu_align_kernel<<<1, 1>>>();

    // Persistent recurrence: all 512 steps in one kernel
    lstm_persistent_kernel<<<NCTAS, NTHR, SMEM_TOTAL>>>(H1, H2, H3, H4, out);
}